// round 12
// baseline (speedup 1.0000x reference)
#include <cuda_runtime.h>
#include <float.h>

// ROI adaptive max pool 7x7 — fine-grained decomposition for load balance.
// Block = (channel-group cg, output-bin-row i, roi). Each block handles the
// 2-8 image rows of ONE bin-row for 32 channels: row-max into smem, then the
// 7 column bins -> 32x7 outputs. 14336 small near-uniform blocks (~24 waves)
// kill the straggler tail that 4096 variable-size blocks (~4.6 waves) had.
// images: [8,256,56,56] f32; rois: [256,4] f32; roi_idx: [256] i32
// out: [256,256,7,7] f32

#define Hc 56
#define Wc 56
#define Cc 256
#define Rc 256
#define OUTN 7
#define CPB 32
#define W4 (Wc / 4)   // 14

__device__ __forceinline__ float4 fm4(float4 a, float4 b) {
    return make_float4(fmaxf(a.x, b.x), fmaxf(a.y, b.y),
                       fmaxf(a.z, b.z), fmaxf(a.w, b.w));
}

__global__ __launch_bounds__(512, 4) void roipool_kernel(
    const float* __restrict__ images,
    const float* __restrict__ rois,
    const int* __restrict__ roi_idx,
    float* __restrict__ out)
{
    __shared__ float rowp[CPB][60];   // row-bin maxes, absolute x indexing

    const int cg = blockIdx.x;        // 0..7  (32 channels each)
    const int i  = blockIdx.y;        // 0..6  output bin-row
    const int r  = blockIdx.z;        // 0..255 roi
    const int tx = threadIdx.x;       // 0..15 quad
    const int ty = threadIdx.y;       // 0..31 channel
    const int tid = ty * 16 + tx;

    const float4 rv = ((const float4*)rois)[r];
    const int x1 = (int)floorf(rv.x * (float)Wc);
    const int y1 = (int)floorf(rv.y * (float)Hc);
    const int x2 = (int)ceilf (rv.z * (float)Wc);
    const int y2 = (int)ceilf (rv.w * (float)Hc);
    const int Hr = y2 - y1;
    const int Wr = x2 - x1;

    // This block's bin-row y-range (divide-by-7 -> magic mul)
    const int s = y1 + (i * Hr) / OUTN;
    const int e = y1 + ((i + 1) * Hr + OUTN - 1) / OUTN;
    const int n = e - s;              // 0 iff Hr==0

    const int n_img = roi_idx[r];

    // ---- Phase 1: row-bin maxes for this i, 32 channels x active quads ----
    const int qlo = x1 >> 2;
    const int qhi = (x2 + 3) >> 2;
    if (n > 0 && tx >= qlo && tx < qhi) {
        const float4* __restrict__ p =
            (const float4*)images + (size_t)(n_img * Cc + cg * CPB + ty) * (Hc * W4)
            + s * W4 + tx;
        float4 m = p[0];
        #pragma unroll 2
        for (int y = 1; y < n; y++)
            m = fm4(m, p[y * W4]);
        *(float4*)&rowp[ty][tx * 4] = m;
    }
    __syncthreads();

    // ---- Phase 2: the 7 column bins of this bin-row ----
    if (tid < CPB * OUTN) {
        const int ch = tid / OUTN;
        const int j  = tid - ch * OUTN;
        const int xs = x1 + (j * Wr) / OUTN;
        const int xe = x1 + ((j + 1) * Wr + OUTN - 1) / OUTN;
        float m = -FLT_MAX;
        if (n > 0) {
            const float* __restrict__ rp = rowp[ch];
            for (int x = xs; x < xe; x++)
                m = fmaxf(m, rp[x]);
        }
        out[(((size_t)r * Cc + cg * CPB + ch) * OUTN + i) * OUTN + j] = m;
    }
}

extern "C" void kernel_launch(void* const* d_in, const int* in_sizes, int n_in,
                              void* d_out, int out_size) {
    const float* images  = (const float*)d_in[0];
    const float* rois    = (const float*)d_in[1];
    const int*   roi_idx = (const int*)d_in[2];
    float* out = (float*)d_out;

    dim3 grid(Cc / CPB, OUTN, Rc);   // (8, 7, 256) = 14336 blocks
    dim3 block(16, CPB);             // 512 threads
    roipool_kernel<<<grid, block>>>(images, rois, roi_idx, out);
}

// round 13
// speedup vs baseline: 1.1032x; 1.1032x over previous
#include <cuda_runtime.h>
#include <float.h>

// ROI adaptive max pool 7x7 — image-resident-in-smem inversion.
// Block = (4-channel slab cg, image n). Loads the 4 channel planes (50KB)
// to shared ONCE (each input byte read exactly once from DRAM), then
// computes ALL ROIs of that image directly from shared memory.
// images: [8,256,56,56] f32; rois: [256,4] f32; roi_idx: [256] i32
// out: [256,256,7,7] f32

#define Nn 8
#define Cc 256
#define Hc 56
#define Wc 56
#define HWc (Hc * Wc)        // 3136
#define Rc 256
#define OUTN 7
#define CPB 4                // channels per block
#define PSTRIDE 3140         // plane stride in floats (3136 + 4 pad: kills
                             // 4-way cross-channel bank conflicts, keeps 16B align)

#define SMEM_BYTES (CPB * PSTRIDE * 4 + Rc * 4 + Rc * 2 + 16)

__global__ __launch_bounds__(512, 4) void roipool_kernel(
    const float* __restrict__ images,
    const float* __restrict__ rois,
    const int* __restrict__ roi_idx,
    float* __restrict__ out)
{
    extern __shared__ char sm[];
    float*          plane = (float*)sm;                        // [4][3140]
    unsigned int*   spack = (unsigned int*)(sm + CPB * PSTRIDE * 4);  // [256]
    unsigned short* sroi  = (unsigned short*)(spack + Rc);     // [256]
    int*            cnt   = (int*)(sroi + Rc);

    const int cg  = blockIdx.x;       // 0..63  (4 channels each)
    const int n   = blockIdx.y;       // 0..7   image
    const int tid = threadIdx.x;      // 0..511

    if (tid == 0) *cnt = 0;
    __syncthreads();

    // ---- Build this image's ROI list (compaction; order-independent) ----
    if (tid < Rc && roi_idx[tid] == n) {
        const float4 rv = ((const float4*)rois)[tid];
        const int x1 = (int)floorf(rv.x * (float)Wc);
        const int y1 = (int)floorf(rv.y * (float)Hc);
        const int x2 = (int)ceilf (rv.z * (float)Wc);
        const int y2 = (int)ceilf (rv.w * (float)Hc);
        const int pos = atomicAdd(cnt, 1);
        spack[pos] = (unsigned)x1 | ((unsigned)y1 << 8)
                   | ((unsigned)(y2 - y1) << 16) | ((unsigned)(x2 - x1) << 24);
        sroi[pos] = (unsigned short)tid;
    }

    // ---- Load 4 contiguous channel planes to shared (coalesced float4) ----
    {
        const float4* __restrict__ src =
            (const float4*)(images + ((size_t)n * Cc + cg * CPB) * HWc);
        #pragma unroll
        for (int k = 0; k < 2; k++) {                 // 2*512 >= 784 per ch? no:
            // 3136 float4 total; strided loop below covers all
        }
        for (int idx = tid; idx < CPB * (HWc / 4); idx += 512) {
            const int cl = idx / (HWc / 4);           // constant divide (784)
            const int w  = idx - cl * (HWc / 4);
            *(float4*)&plane[cl * PSTRIDE + w * 4] = src[idx];
        }
    }
    __syncthreads();

    const int nLocal = *cnt;
    const int total  = nLocal * (CPB * OUTN * OUTN);  // nLocal * 196

    // ---- Pool all ROIs straight from shared ----
    for (int o = tid; o < total; o += 512) {
        const int rl  = o / 196;                      // constant magic mul
        const int rem = o - rl * 196;
        const int ch  = rem / 49;
        const int b   = rem - ch * 49;
        const int i   = b / 7;
        const int j   = b - i * 7;

        const unsigned pk = spack[rl];
        const int x1 = pk & 255;
        const int y1 = (pk >> 8) & 255;
        const int Hr = (pk >> 16) & 255;
        const int Wr = pk >> 24;

        const int ys = y1 + (i * Hr) / OUTN;
        const int ye = y1 + ((i + 1) * Hr + OUTN - 1) / OUTN;
        const int xs = x1 + (j * Wr) / OUTN;
        const int xe = x1 + ((j + 1) * Wr + OUTN - 1) / OUTN;

        const float* __restrict__ sp = plane + ch * PSTRIDE;
        float m = -FLT_MAX;
        for (int y = ys; y < ye; y++) {
            const float* __restrict__ row = sp + y * Wc;
            #pragma unroll 4
            for (int x = xs; x < xe; x++)
                m = fmaxf(m, row[x]);
        }

        const int rg = sroi[rl];
        out[((size_t)rg * Cc + cg * CPB + ch) * 49 + b] = m;
    }
}

extern "C" void kernel_launch(void* const* d_in, const int* in_sizes, int n_in,
                              void* d_out, int out_size) {
    const float* images  = (const float*)d_in[0];
    const float* rois    = (const float*)d_in[1];
    const int*   roi_idx = (const int*)d_in[2];
    float* out = (float*)d_out;

    cudaFuncSetAttribute(roipool_kernel,
                         cudaFuncAttributeMaxDynamicSharedMemorySize, SMEM_BYTES);

    dim3 grid(Cc / CPB, Nn);    // (64, 8) = 512 blocks
    roipool_kernel<<<grid, 512, SMEM_BYTES>>>(images, rois, roi_idx, out);
}

// round 14
// speedup vs baseline: 1.1548x; 1.0468x over previous
#include <cuda_runtime.h>
#include <float.h>

// ROI adaptive max pool 7x7 — densely-packed phase-1 threads.
// images: [8,256,56,56] f32; rois: [256,4] f32; roi_idx: [256] i32
// out: [256,256,7,7] f32
//
// Block = (roi, 32-channel group), 256 flat threads, grid (8,256)=2048.
// Phase 1 (per column-octave pass, nqp = #active quads <= 8):
//   active threads are CONTIGUOUS: tid < 32*nqp, ch = tid/nqp, q = tid%nqp.
//   Inactive threads form whole warps that skip to the barrier (zero issue),
//   unlike fixed quad-slot mapping where ~64% of lanes idle inside warps.
//   Body = proven R8 switch (trip-count-specialized, batched loads).
// Phase 2: pass-clipped col-bin maxes accumulated in sout; float4 writeback.

#define Hc 56
#define Wc 56
#define Cc 256
#define Rc 256
#define OUTN 7
#define CPB 32
#define W4 (Wc / 4)     // 14
#define CHW4 (Hc * W4)  // 784 float4 per channel
#define RW 36           // rowp inner stride (floats; 16B-aligned slots)

__device__ __forceinline__ float4 fm4(float4 a, float4 b) {
    return make_float4(fmaxf(a.x, b.x), fmaxf(a.y, b.y),
                       fmaxf(a.z, b.z), fmaxf(a.w, b.w));
}

__global__ __launch_bounds__(256) void roipool_kernel(
    const float* __restrict__ images,
    const float* __restrict__ rois,
    const int* __restrict__ roi_idx,
    float* __restrict__ out)
{
    __shared__ float rowp[CPB][OUTN][RW];   // 32.25 KB, slots for 8 quads
    __shared__ float sout[CPB * 49];        // 6.27 KB
    __shared__ int sb[28];                  // ys[7] ye[7] xs[7] xe[7]

    const int r   = blockIdx.y;
    const int cg  = blockIdx.x;
    const int tid = threadIdx.x;

    const float4 rv = ((const float4*)rois)[r];
    const int x1 = (int)floorf(rv.x * (float)Wc);
    const int y1 = (int)floorf(rv.y * (float)Hc);
    const int x2 = (int)ceilf (rv.z * (float)Wc);
    const int y2 = (int)ceilf (rv.w * (float)Hc);

    if (tid < 28) {
        const int g = tid / OUTN;           // 0:ys 1:ye 2:xs 3:xe
        const int i = tid - g * OUTN;
        const int Hr = y2 - y1, Wr = x2 - x1;
        int v;
        if (g == 0)      v = y1 + (i * Hr) / OUTN;
        else if (g == 1) v = y1 + ((i + 1) * Hr + OUTN - 1) / OUTN;
        else if (g == 2) v = x1 + (i * Wr) / OUTN;
        else             v = x1 + ((i + 1) * Wr + OUTN - 1) / OUTN;
        sb[tid] = v;
    }
    __syncthreads();

    const int qlo = x1 >> 2;
    const int qhi = (x2 + 3) >> 2;
    const int nq  = qhi - qlo;              // 0..14
    const int npass = (nq <= 8) ? 1 : 2;

    const int n_img = roi_idx[r];
    const float4* __restrict__ img4 =
        (const float4*)images + (size_t)(n_img * Cc + cg * CPB) * CHW4;

    for (int p = 0; p < npass; p++) {
        const int qbase = qlo + p * 8;
        int nqp = nq - p * 8; if (nqp > 8) nqp = 8;   // may be 0 only if nq==0

        // ---- Phase 1: densely packed (ch, q) over active quads ----
        if (tid < CPB * nqp) {
            const int d  = nqp;             // >=1 here
            const int ch = tid / d;
            const int q  = tid - ch * d;
            const float4* __restrict__ base = img4 + ch * CHW4 + (qbase + q);
            #pragma unroll
            for (int i = 0; i < OUTN; i++) {
                const int s = sb[i];
                const int n = sb[7 + i] - s;    // block-uniform, >=0
                const float4* __restrict__ pp = base + s * W4;
                float4 m;
                switch (n) {
                case 1: m = pp[0]; break;
                case 2: m = fm4(pp[0], pp[W4]); break;
                case 3: m = fm4(fm4(pp[0], pp[W4]), pp[2 * W4]); break;
                case 4: m = fm4(fm4(pp[0], pp[W4]),
                                fm4(pp[2 * W4], pp[3 * W4])); break;
                default: {
                    m = make_float4(-FLT_MAX, -FLT_MAX, -FLT_MAX, -FLT_MAX);
                    if (n > 0) {
                        m = pp[0];
                        #pragma unroll 2
                        for (int y = 1; y < n; y++)
                            m = fm4(m, pp[y * W4]);
                    }
                } break;
                }
                *(float4*)&rowp[ch][i][q * 4] = m;   // stride RW=36 keeps 16B align
            }
        }
        __syncthreads();

        // ---- Phase 2 partial: col bins clipped to this pass's x-range ----
        const int x0 = qbase * 4;
        const int xm = x0 + nqp * 4;
        for (int o = tid; o < CPB * 49; o += 256) {
            const int ch = o / 49;
            const int b  = o - ch * 49;
            const int i  = b / 7;
            const int j  = b - i * 7;
            int xs = sb[14 + j]; if (xs < x0) xs = x0;
            int xe = sb[21 + j]; if (xe > xm) xe = xm;
            float m = (p == 0) ? -FLT_MAX : sout[o];
            const float* __restrict__ rp = &rowp[ch][i][0];
            for (int x = xs; x < xe; x++)
                m = fmaxf(m, rp[x - x0]);
            sout[o] = m;
        }
        __syncthreads();   // protect rowp before next pass / writeback order
    }

    // ---- Coalesced writeback of contiguous [32ch x 49] slab ----
    float4* __restrict__ og = (float4*)(out + ((size_t)r * Cc + cg * CPB) * 49);
    const float4* __restrict__ so4 = (const float4*)sout;
    #pragma unroll
    for (int idx = tid; idx < CPB * 49 / 4; idx += 256)
        og[idx] = so4[idx];
}

extern "C" void kernel_launch(void* const* d_in, const int* in_sizes, int n_in,
                              void* d_out, int out_size) {
    const float* images  = (const float*)d_in[0];
    const float* rois    = (const float*)d_in[1];
    const int*   roi_idx = (const int*)d_in[2];
    float* out = (float*)d_out;

    dim3 grid(Cc / CPB, Rc);   // (8, 256) = 2048 blocks
    roipool_kernel<<<grid, 256>>>(images, rois, roi_idx, out);
}

// round 15
// speedup vs baseline: 1.3900x; 1.2037x over previous
#include <cuda_runtime.h>
#include <float.h>

// ROI adaptive max pool 7x7 — R5/R8 mapping with warp-private pipelines:
// each warp (16 quads x 2 channels) produces and consumes its own rowp,
// so block barriers are replaced by __syncwarp. Warps drift out of phase,
// interleaving their load bursts -> higher issue duty cycle.
// images: [8,256,56,56] f32; rois: [256,4] f32; roi_idx: [256] i32
// out: [256,256,7,7] f32

#define Hc 56
#define Wc 56
#define Cc 256
#define Rc 256
#define OUTN 7
#define CPB 16
#define W4 (Wc / 4)   // 14

__device__ __forceinline__ float4 fm4(float4 a, float4 b) {
    return make_float4(fmaxf(a.x, b.x), fmaxf(a.y, b.y),
                       fmaxf(a.z, b.z), fmaxf(a.w, b.w));
}

__global__ __launch_bounds__(256, 8) void roipool_kernel(
    const float* __restrict__ images,
    const float* __restrict__ rois,
    const int* __restrict__ roi_idx,
    float* __restrict__ out)
{
    __shared__ float rowp[CPB][OUTN][60];

    const int r  = blockIdx.y;
    const int cg = blockIdx.x;
    const int tx = threadIdx.x;            // 0..15 quad
    const int ty = threadIdx.y;            // 0..15 channel
    const int lane = (ty & 1) * 16 + tx;   // lane within warp
    // warp w covers channels {2w, 2w+1}: ty = 2w + (lane>=16)

    // Per-thread ROI math (registers only; no shared table, no barrier)
    const float4 rv = ((const float4*)rois)[r];
    const int x1 = (int)floorf(rv.x * (float)Wc);
    const int y1 = (int)floorf(rv.y * (float)Hc);
    const int x2 = (int)ceilf (rv.z * (float)Wc);
    const int y2 = (int)ceilf (rv.w * (float)Hc);
    const int Hr = y2 - y1;
    const int Wr = x2 - x1;

    const int n_img = roi_idx[r];
    const float* __restrict__ img =
        images + (size_t)(n_img * Cc + cg * CPB + ty) * (Hc * Wc);

    // ---- Phase 1: row-bin maxes (trip-count-specialized switch) ----
    const int qlo = x1 >> 2;
    const int qhi = (x2 + 3) >> 2;
    if (tx >= qlo && tx < qhi) {
        const float4* __restrict__ base = (const float4*)img + tx;
        #pragma unroll
        for (int i = 0; i < OUTN; i++) {
            const int s = y1 + (i * Hr) / OUTN;
            const int n = (y1 + ((i + 1) * Hr + OUTN - 1) / OUTN) - s;  // >=1
            const float4* __restrict__ p = base + s * W4;
            float4 m;
            switch (n) {
            case 1: m = p[0]; break;
            case 2: m = fm4(p[0], p[W4]); break;
            case 3: m = fm4(fm4(p[0], p[W4]), p[2 * W4]); break;
            case 4: m = fm4(fm4(p[0], p[W4]), fm4(p[2 * W4], p[3 * W4])); break;
            default: {
                m = p[0];
                #pragma unroll 2
                for (int y = 1; y < n; y++)
                    m = fm4(m, p[y * W4]);
            } break;
            }
            *(float4*)&rowp[ty][i][tx * 4] = m;
        }
    }
    __syncwarp();   // warp-private rowp: no block barrier needed

    // ---- Phase 2: col-bin maxes for this warp's 2 channels ----
    // outputs o in [0,98): ch_sel = o>=49, b = o-49*ch_sel
    const int ch0 = ty & ~1;               // even channel of this warp
    float* __restrict__ outg =
        out + ((size_t)r * Cc + cg * CPB + ch0) * (OUTN * OUTN);
    #pragma unroll
    for (int k = 0; k < 4; k++) {
        const int o = lane + k * 32;
        if (o < 98) {
            const int csel = (o >= 49);
            const int b = o - csel * 49;
            const int i = (b * 37) >> 8;   // b/7 for b<=48
            const int j = b - i * OUTN;
            const int s = x1 + (j * Wr) / OUTN;
            const int n = (x1 + ((j + 1) * Wr + OUTN - 1) / OUTN) - s;  // >=1
            const float* __restrict__ rp = &rowp[ch0 + csel][i][s];
            float m;
            switch (n) {
            case 1: m = rp[0]; break;
            case 2: m = fmaxf(rp[0], rp[1]); break;
            case 3: m = fmaxf(fmaxf(rp[0], rp[1]), rp[2]); break;
            case 4: m = fmaxf(fmaxf(rp[0], rp[1]), fmaxf(rp[2], rp[3])); break;
            default: {
                m = rp[0];
                #pragma unroll 2
                for (int x = 1; x < n; x++)
                    m = fmaxf(m, rp[x]);
            } break;
            }
            outg[o] = m;   // 98 contiguous floats per warp -> coalesced runs
        }
    }
}

extern "C" void kernel_launch(void* const* d_in, const int* in_sizes, int n_in,
                              void* d_out, int out_size) {
    const float* images  = (const float*)d_in[0];
    const float* rois    = (const float*)d_in[1];
    const int*   roi_idx = (const int*)d_in[2];
    float* out = (float*)d_out;

    dim3 grid(Cc / CPB, Rc);   // (16, 256) = 4096 blocks
    dim3 block(16, 16);        // 256 threads
    roipool_kernel<<<grid, block>>>(images, rois, roi_idx, out);
}